// round 13
// baseline (speedup 1.0000x reference)
#include <cuda_runtime.h>
#include <cuda_fp16.h>
#include <cstdint>

#define IN_DIM  2048
#define HDIM    8192
#define OUT_DIM 512
#define NBATCH  4096

typedef __half fp16;

// ---------------- scratch (static __device__ per harness rules) ----------------
__device__ __align__(256) fp16 g_xhi [(size_t)NBATCH * IN_DIM];
__device__ __align__(256) fp16 g_xlo [(size_t)NBATCH * IN_DIM];
__device__ __align__(256) fp16 g_W1hi[(size_t)IN_DIM * HDIM];     // Ŵ1 = W1/s1
__device__ __align__(256) fp16 g_W1Thi[(size_t)HDIM * IN_DIM];
__device__ __align__(256) fp16 g_W2Thi[(size_t)OUT_DIM * HDIM];   // Ŵ2ᵀ = (W2/s2)ᵀ
__device__ __align__(256) fp16 g_z1hi[(size_t)NBATCH * HDIM];
__device__ __align__(256) fp16 g_zhi [(size_t)NBATCH * OUT_DIM];
__device__ __align__(256) fp16 g_zlo [(size_t)NBATCH * OUT_DIM];
__device__ __align__(256) float g_part[(size_t)4 * NBATCH * OUT_DIM]; // K-split partials (GM & G2)
__device__ __align__(256) fp16 g_Mhi [(size_t)IN_DIM * OUT_DIM];  // M̂ = Ŵ1@Ŵ2
__device__ __align__(256) float g_dvec[IN_DIM];                   // db1@W1ᵀ + db2
__device__ int g_maskmode;

// ---------------- PTX helpers (compute_100-safe) ----------------
__device__ __forceinline__ uint32_t smem_u32(const void* p) {
    uint32_t a;
    asm("{ .reg .u64 t; cvta.to.shared.u64 t, %1; cvt.u32.u64 %0, t; }" : "=r"(a) : "l"(p));
    return a;
}
#define SWZ128(off) ((off) ^ (((off) >> 3) & 0x70))

__device__ __forceinline__ void cp16cp(uint32_t dst, const void* src) {
    asm volatile("cp.async.cg.shared.global [%0], [%1], 16;" :: "r"(dst), "l"(src));
}
#define CP_COMMIT() asm volatile("cp.async.commit_group;" ::: "memory")
#define CP_WAIT(n)  asm volatile("cp.async.wait_group %0;" :: "n"(n) : "memory")

__device__ __forceinline__ void ldsm4(uint32_t a, uint32_t& r0, uint32_t& r1,
                                      uint32_t& r2, uint32_t& r3) {
    asm volatile("ldmatrix.sync.aligned.m8n8.x4.shared.b16 {%0,%1,%2,%3}, [%4];"
                 : "=r"(r0), "=r"(r1), "=r"(r2), "=r"(r3) : "r"(a));
}

__device__ __forceinline__ void mma16816(float* d, const uint32_t* a, const uint32_t* b) {
    asm volatile("mma.sync.aligned.m16n8k16.row.col.f32.f16.f16.f32 "
        "{%0,%1,%2,%3}, {%4,%5,%6,%7}, {%8,%9}, {%0,%1,%2,%3};"
        : "+f"(d[0]), "+f"(d[1]), "+f"(d[2]), "+f"(d[3])
        : "r"(a[0]), "r"(a[1]), "r"(a[2]), "r"(a[3]), "r"(b[0]), "r"(b[1]));
}

// ---------------- mask dtype detection ----------------
__global__ void detect_mask_kernel(const unsigned int* __restrict__ m, int nwords) {
    __shared__ int ok[4];
    if (threadIdx.x < 4) ok[threadIdx.x] = 1;
    __syncthreads();
    for (int i = threadIdx.x; i < nwords; i += blockDim.x) {
        unsigned w = m[i];
        if (!(w == 0u || w == 1u))          atomicAnd(&ok[0], 0);
        if (!(w == 0u || w == 0x3F800000u)) atomicAnd(&ok[1], 0);
        unsigned lo = w & 0xFFFFu, hi = w >> 16;
        if (!((lo == 0u || lo == 0x3F80u) && (hi == 0u || hi == 0x3F80u))) atomicAnd(&ok[2], 0);
        if (!((lo == 0u || lo == 0x3C00u) && (hi == 0u || hi == 0x3C00u))) atomicAnd(&ok[3], 0);
    }
    __syncthreads();
    if (threadIdx.x == 0) {
        int mode = 0;
        if      (ok[0]) mode = 1;
        else if (ok[1]) mode = 2;
        else if (ok[2]) mode = 3;
        else if (ok[3]) mode = 4;
        g_maskmode = mode;
    }
}

__device__ __forceinline__ int read_mask(const void* p, long i, int mode) {
    switch (mode) {
        case 1:  return ((const int*)p)[i] != 0;
        case 2:  return ((const float*)p)[i] != 0.0f;
        case 3:  return ((const unsigned short*)p)[i] != 0;
        case 4:  return ((const unsigned short*)p)[i] != 0;
        default: return ((const unsigned char*)p)[i] != 0;
    }
}

__device__ __forceinline__ void split2h(float v, fp16& h, fp16& l) {
    h = __float2half(v);
    l = __float2half(v - __half2float(h));
}

// ---------------- fused prepass: split x | dequant W1 | dequant W2 ----------
// Flat grid of 256-thread blocks:
//   [0, NB_SPLIT)                : split x (vectorized float4)
//   [NB_SPLIT, NB_SPLIT+NB_DQ1)  : dequant W1 -> W1hi + W1Thi
//   [.., +NB_DQ2)                : dequant W2 -> W2Thi
#define NB_SPLIT (NBATCH * IN_DIM / 4 / 256)      // 8192
#define NB_DQ1   ((HDIM / 32) * (IN_DIM / 32))    // 16384
#define NB_DQ2   ((OUT_DIM / 32) * (HDIM / 32))   // 4096

__device__ __forceinline__ void dequant_block(
    const int* __restrict__ idx, const void* __restrict__ mask,
    const float* __restrict__ wf, const float* __restrict__ cb,
    fp16* __restrict__ Whi, fp16* __restrict__ WThi,
    int R, int C, int bx, int by, float tile[32][33]) {
    const int mode = g_maskmode;
    float s = __ldg(cb + 3);
    if (s == 0.0f) s = 1.0f;
    const int c0 = bx * 32;
    const int r0 = by * 32;
    const int tx = threadIdx.x & 31;
    const int ty = threadIdx.x >> 5;      // 0..7
    for (int rr = ty; rr < 32; rr += 8) {
        long off = (long)(r0 + rr) * C + c0 + tx;
        int  m = read_mask(mask, off, mode);
        float v = (m ? cb[idx[off]] : wf[off]) / s;   // exact for codebook
        if (Whi) Whi[off] = __float2half(v);
        tile[rr][tx] = v;
    }
    __syncthreads();
    for (int rr = ty; rr < 32; rr += 8) {
        float v = tile[tx][rr];
        long off = (long)(c0 + rr) * R + r0 + tx;
        WThi[off] = __float2half(v);
    }
}

__global__ void prepass_kernel(
    const float4* __restrict__ x4, fp16* __restrict__ xhi, fp16* __restrict__ xlo,
    const int* __restrict__ W1i, const void* __restrict__ W1m,
    const float* __restrict__ W1f, const float* __restrict__ cb1,
    fp16* __restrict__ W1hi, fp16* __restrict__ W1Thi,
    const int* __restrict__ W2i, const void* __restrict__ W2m,
    const float* __restrict__ W2f, const float* __restrict__ cb2,
    fp16* __restrict__ W2Thi) {
    __shared__ float tile[32][33];
    const int b = blockIdx.x;
    if (b < NB_SPLIT) {
        size_t i = (size_t)b * 256 + threadIdx.x;
        float4 v = x4[i];
        fp16 h0, l0, h1, l1, h2, l2, h3, l3;
        split2h(v.x, h0, l0); split2h(v.y, h1, l1);
        split2h(v.z, h2, l2); split2h(v.w, h3, l3);
        ((__half2*)xhi)[2 * i]     = __halves2half2(h0, h1);
        ((__half2*)xhi)[2 * i + 1] = __halves2half2(h2, h3);
        ((__half2*)xlo)[2 * i]     = __halves2half2(l0, l1);
        ((__half2*)xlo)[2 * i + 1] = __halves2half2(l2, l3);
    } else if (b < NB_SPLIT + NB_DQ1) {
        int j = b - NB_SPLIT;
        dequant_block(W1i, W1m, W1f, cb1, W1hi, W1Thi,
                      IN_DIM, HDIM, j & 255, j >> 8, tile);
    } else {
        int j = b - NB_SPLIT - NB_DQ1;
        dequant_block(W2i, W2m, W2f, cb2, nullptr, W2Thi,
                      HDIM, OUT_DIM, j & 15, j >> 4, tile);
    }
}

// ---------------- fused post-GM: reduce M partials | dvec ----------------
// [0, NB_RM): Mhi[i] = half(sum of 4 partials);  [NB_RM, NB_RM+IN_DIM): dvec rows
#define NB_RM ((IN_DIM * OUT_DIM) / 256)          // 4096

__global__ void postgm_kernel(const float* __restrict__ part,
                              fp16* __restrict__ Mhi,
                              const fp16* __restrict__ W1hi,
                              const float* __restrict__ db1, const float* __restrict__ db2,
                              const float* __restrict__ cb1, float* __restrict__ dvec) {
    __shared__ float red[256];
    const int b = blockIdx.x;
    if (b < NB_RM) {
        size_t i = (size_t)b * 256 + threadIdx.x;
        const size_t n = (size_t)IN_DIM * OUT_DIM;
        float v = part[i] + part[i + n] + part[i + 2 * n] + part[i + 3 * n];
        Mhi[i] = __float2half(v);
    } else {
        const int j = b - NB_RM;
        float s = __ldg(cb1 + 3);
        if (s == 0.0f) s = 1.0f;
        float sum = 0.0f;
        const size_t base = (size_t)j * HDIM;
        for (int h = threadIdx.x; h < HDIM; h += 256)
            sum += __half2float(W1hi[base + h]) * __ldg(db1 + h);
        red[threadIdx.x] = sum;
        __syncthreads();
        for (int st = 128; st > 0; st >>= 1) {
            if (threadIdx.x < st) red[threadIdx.x] += red[threadIdx.x + st];
            __syncthreads();
        }
        if (threadIdx.x == 0) dvec[j] = fmaf(s, red[0], __ldg(db2 + j));
    }
}

// ---------------- reduce G2 partials: z = s2*Σ + b2, + fp16 split ----------
__global__ void reduce_z_kernel(const float* __restrict__ part,
                                const float* __restrict__ cb2,
                                const float* __restrict__ b2,
                                float* __restrict__ z,
                                fp16* __restrict__ zhi, fp16* __restrict__ zlo) {
    size_t i = (size_t)blockIdx.x * blockDim.x + threadIdx.x;
    const size_t n = (size_t)NBATCH * OUT_DIM;
    if (i < n) {
        float s = __ldg(cb2 + 3);
        if (s == 0.0f) s = 1.0f;
        float acc = part[i] + part[i + n] + part[i + 2 * n] + part[i + 3 * n];
        float v = fmaf(s, acc, __ldg(b2 + (i % OUT_DIM)));
        z[i] = v;
        fp16 h, l; split2h(v, h, l);
        zhi[i] = h; zlo[i] = l;
    }
}

// ---------------- c19 activation ----------------
__device__ __forceinline__ float c19f(float x, float craw, float rhoraw) {
    float c   = fmaxf(craw, 0.1f);
    float rho = fmaxf(rhoraw, 0.0f);
    float L   = 6.0f * c;
    float s   = x / c;
    float n   = floorf(s);
    float t   = s - n;
    float h   = t * (1.0f - t);
    float sgn = (fmodf(n, 2.0f) == 0.0f) ? 1.0f : -1.0f;
    float interior = c * (sgn * h + rho * h * h);
    return (x >= L) ? (x - L) : ((x <= -L) ? (x + L) : interior);
}

// ---------------- fp16 multi-product GEMM ----------------
// acc = Ahi*Bhi (+ Alo*Bhi if PA==2) (+ Ahi*Blo if PB==2)
// C = sa*sb*acc + bias (nullable). B K-major. Block 128 x (NI*32), 8 warps 2x4.
// gridDim.z = K-splits (partials at Cf + z*M*Nn). ldk = row stride of A and B.
#define BM 128
#define BKK 32

template<int NI, int PA, int PB, int NSTAGE>
__global__ void __launch_bounds__(256, 1)
gemm_fp16_kernel(const fp16* __restrict__ Ahi, const fp16* __restrict__ Alo,
                 const fp16* __restrict__ Bhi, const fp16* __restrict__ Blo,
                 int M, int Nn, int Klen, int ldk,
                 const float* __restrict__ cba, const float* __restrict__ cbb,
                 const float* __restrict__ bias, int epi,
                 const float* __restrict__ craw, const float* __restrict__ rho,
                 float* __restrict__ Cf, fp16* __restrict__ Chi, fp16* __restrict__ Clo) {
    constexpr int BN = NI * 32;
    constexpr int A_BYTES = BM * 64;
    constexpr int B_BYTES = BN * 64;
    constexpr int STAGE_BYTES = PA * A_BYTES + PB * B_BYTES;
    extern __shared__ char smem[];
    const uint32_t sbase = smem_u32(smem);
    const uint32_t tbase = (sbase + 1023u) & ~1023u;
    const int tid  = threadIdx.x;
    const int wid  = tid >> 5;
    const int lane = tid & 31;
    const int wm = wid & 1;
    const int wn = wid >> 1;

    const int m0 = blockIdx.y * BM;
    const int n0 = blockIdx.x * BN;
    const size_t kbase = (size_t)blockIdx.z * Klen;

    float sa = cba ? __ldg(cba + 3) : 1.0f;  if (sa == 0.0f) sa = 1.0f;
    float sb = cbb ? __ldg(cbb + 3) : 1.0f;  if (sb == 0.0f) sb = 1.0f;
    const float sc = sa * sb;

    uint32_t sAh[NSTAGE], sAl[NSTAGE], sBh[NSTAGE], sBl[NSTAGE];
#pragma unroll
    for (int s = 0; s < NSTAGE; s++) {
        uint32_t b = tbase + s * STAGE_BYTES;
        sAh[s] = b;
        sAl[s] = b + A_BYTES;                         // valid if PA==2
        sBh[s] = b + PA * A_BYTES;
        sBl[s] = b + PA * A_BYTES + B_BYTES;          // valid if PB==2
    }

    const int ITERS = Klen / BKK;

    float acc[4][NI][4];
#pragma unroll
    for (int i = 0; i < 4; i++)
#pragma unroll
        for (int j = 0; j < NI; j++)
#pragma unroll
            for (int r = 0; r < 4; r++) acc[i][j][r] = 0.0f;

    auto fill = [&](int kc) {
        const int s = kc % NSTAGE;
        const size_t k0 = kbase + (size_t)kc * BKK;
#pragma unroll
        for (int i = 0; i < 2; i++) {
            int ch = tid + i * 256;
            int r = ch >> 2, c = ch & 3;
            uint32_t so = SWZ128(r * 64 + c * 16);
            const char* pA = (const char*)(Ahi + (size_t)(m0 + r) * ldk + k0) + c * 16;
            cp16cp(sAh[s] + so, pA);
            if (PA == 2) {
                const char* pL = (const char*)(Alo + (size_t)(m0 + r) * ldk + k0) + c * 16;
                cp16cp(sAl[s] + so, pL);
            }
        }
#pragma unroll
        for (int i = 0; i < NI / 2; i++) {
            int ch = tid + i * 256;
            int r = ch >> 2, c = ch & 3;
            uint32_t so = SWZ128(r * 64 + c * 16);
            const char* pB = (const char*)(Bhi + (size_t)(n0 + r) * ldk + k0) + c * 16;
            cp16cp(sBh[s] + so, pB);
            if (PB == 2) {
                const char* pBl = (const char*)(Blo + (size_t)(n0 + r) * ldk + k0) + c * 16;
                cp16cp(sBl[s] + so, pBl);
            }
        }
    };

    // prologue
    for (int it = 0; it < NSTAGE - 1; it++) { fill(it); CP_COMMIT(); }

    for (int it = 0; it < ITERS; it++) {
        CP_WAIT(NSTAGE - 2);
        __syncthreads();
        if (it + NSTAGE - 1 < ITERS) fill(it + NSTAGE - 1);
        CP_COMMIT();

        const int s = it % NSTAGE;
#pragma unroll
        for (int kk = 0; kk < 2; kk++) {
            uint32_t afh[4][4], afl[4][4];
#pragma unroll
            for (int mi = 0; mi < 4; mi++) {
                int row = wm * 64 + mi * 16 + (lane & 15);
                int ch  = kk * 2 + (lane >> 4);
                uint32_t so = SWZ128(row * 64 + ch * 16);
                ldsm4(sAh[s] + so, afh[mi][0], afh[mi][1], afh[mi][2], afh[mi][3]);
                if (PA == 2)
                    ldsm4(sAl[s] + so, afl[mi][0], afl[mi][1], afl[mi][2], afl[mi][3]);
            }
            uint32_t bfh[NI][2], bfl[NI][2];
#pragma unroll
            for (int p = 0; p < NI / 2; p++) {
                int g   = lane >> 3;
                int row = wn * (NI * 8) + (p * 2 + (g >> 1)) * 8 + (lane & 7);
                int ch  = kk * 2 + (g & 1);
                uint32_t so = SWZ128(row * 64 + ch * 16);
                uint32_t r0, r1, r2, r3;
                ldsm4(sBh[s] + so, r0, r1, r2, r3);
                bfh[p * 2][0] = r0;  bfh[p * 2][1] = r1;
                bfh[p * 2 + 1][0] = r2; bfh[p * 2 + 1][1] = r3;
                if (PB == 2) {
                    ldsm4(sBl[s] + so, r0, r1, r2, r3);
                    bfl[p * 2][0] = r0;  bfl[p * 2][1] = r1;
                    bfl[p * 2 + 1][0] = r2; bfl[p * 2 + 1][1] = r3;
                }
            }
#pragma unroll
            for (int mi = 0; mi < 4; mi++)
#pragma unroll
                for (int ni = 0; ni < NI; ni++)
                    mma16816(acc[mi][ni], afh[mi], bfh[ni]);
            if (PA == 2) {
#pragma unroll
                for (int mi = 0; mi < 4; mi++)
#pragma unroll
                    for (int ni = 0; ni < NI; ni++)
                        mma16816(acc[mi][ni], afl[mi], bfh[ni]);
            }
            if (PB == 2) {
#pragma unroll
                for (int mi = 0; mi < 4; mi++)
#pragma unroll
                    for (int ni = 0; ni < NI; ni++)
                        mma16816(acc[mi][ni], afh[mi], bfl[ni]);
            }
        }
    }

    // ---------------- epilogue: scale + bias (+c19) + outputs ----------------
    float* CfZ = Cf ? Cf + (size_t)blockIdx.z * M * Nn : nullptr;
#pragma unroll
    for (int ni = 0; ni < NI; ni++) {
        const int n = n0 + wn * (NI * 8) + ni * 8 + 2 * (lane & 3);
        const float bv0 = bias ? __ldg(bias + n)     : 0.0f;
        const float bv1 = bias ? __ldg(bias + n + 1) : 0.0f;
        float c0 = 0, c1 = 0, r0 = 0, r1 = 0;
        if (epi) {
            c0 = __ldg(craw + n);  c1 = __ldg(craw + n + 1);
            r0 = __ldg(rho + n);   r1 = __ldg(rho + n + 1);
        }
#pragma unroll
        for (int mi = 0; mi < 4; mi++) {
#pragma unroll
            for (int h = 0; h < 2; h++) {
                const int m = m0 + wm * 64 + mi * 16 + (lane >> 2) + h * 8;
                float v0 = fmaf(sc, acc[mi][ni][2 * h],     bv0);
                float v1 = fmaf(sc, acc[mi][ni][2 * h + 1], bv1);
                if (epi) { v0 = c19f(v0, c0, r0); v1 = c19f(v1, c1, r1); }
                const size_t off = (size_t)m * Nn + n;
                if (CfZ) *(float2*)(CfZ + off) = make_float2(v0, v1);
                if (Chi) {
                    fp16 h0, l0, h1, l1;
                    split2h(v0, h0, l0); split2h(v1, h1, l1);
                    *(__half2*)(Chi + off) = __halves2half2(h0, h1);
                    if (Clo) *(__half2*)(Clo + off) = __halves2half2(l0, l1);
                }
            }
        }
    }
}

#define SMEM_CFG(NI, PA, PB, NSTAGE) \
    (1024 + (NSTAGE) * ((PA) * BM * 64 + (PB) * (NI) * 32 * 64))

// ---------------- launch ----------------
extern "C" void kernel_launch(void* const* d_in, const int* in_sizes, int n_in,
                              void* d_out, int out_size) {
    const float* x    = (const float*)d_in[0];
    const float* cb1  = (const float*)d_in[1];
    const float* cb2  = (const float*)d_in[2];
    const float* W1f  = (const float*)d_in[3];
    const float* W2f  = (const float*)d_in[4];
    const float* b1   = (const float*)d_in[5];
    const float* b2   = (const float*)d_in[6];
    const float* db1  = (const float*)d_in[7];
    const float* db2  = (const float*)d_in[8];
    const float* craw = (const float*)d_in[9];
    const float* rraw = (const float*)d_in[10];
    const int*   W1i  = (const int*)d_in[11];
    const int*   W2i  = (const int*)d_in[12];
    const void*  W1m  = d_in[13];
    const void*  W2m  = d_in[14];

    fp16 *xhi, *xlo, *W1hi, *W1Thi, *W2Thi;
    fp16 *z1hi, *zhi, *zlo, *Mhi;
    float *part, *dvec;
    cudaGetSymbolAddress((void**)&xhi,  g_xhi);   cudaGetSymbolAddress((void**)&xlo,  g_xlo);
    cudaGetSymbolAddress((void**)&W1hi, g_W1hi);
    cudaGetSymbolAddress((void**)&W1Thi,g_W1Thi);
    cudaGetSymbolAddress((void**)&W2Thi,g_W2Thi);
    cudaGetSymbolAddress((void**)&z1hi, g_z1hi);
    cudaGetSymbolAddress((void**)&zhi,  g_zhi);   cudaGetSymbolAddress((void**)&zlo,  g_zlo);
    cudaGetSymbolAddress((void**)&part, g_part);
    cudaGetSymbolAddress((void**)&Mhi,  g_Mhi);
    cudaGetSymbolAddress((void**)&dvec, g_dvec);

    float* dec = (float*)d_out;
    float* z   = (float*)d_out + (size_t)NBATCH * IN_DIM;

    cudaFuncSetAttribute((const void*)gemm_fp16_kernel<8,2,1,4>,
                         cudaFuncAttributeMaxDynamicSharedMemorySize, SMEM_CFG(8,2,1,4));
    cudaFuncSetAttribute((const void*)gemm_fp16_kernel<4,1,1,5>,
                         cudaFuncAttributeMaxDynamicSharedMemorySize, SMEM_CFG(4,1,1,5));
    cudaFuncSetAttribute((const void*)gemm_fp16_kernel<4,2,1,4>,
                         cudaFuncAttributeMaxDynamicSharedMemorySize, SMEM_CFG(4,2,1,4));

    // 1. mask dtype probe
    detect_mask_kernel<<<1, 256>>>((const unsigned int*)W1m, 4096);

    // 2. fused prepass: split x | dequant W1 | dequant W2 (overlapped)
    prepass_kernel<<<NB_SPLIT + NB_DQ1 + NB_DQ2, 256>>>(
        (const float4*)x, xhi, xlo,
        W1i, W1m, W1f, cb1, W1hi, W1Thi,
        W2i, W2m, W2f, cb2, W2Thi);

    // 3. GM: M̂ = Ŵ1hi @ Ŵ2hi (1-product, K-split 4)   [2048 x 512], K=8192
    gemm_fp16_kernel<4,1,1,5><<<dim3(OUT_DIM / 128, IN_DIM / BM, 4), 256, SMEM_CFG(4,1,1,5)>>>(
        W1hi, nullptr, W2Thi, nullptr, IN_DIM, OUT_DIM, HDIM / 4, HDIM,
        nullptr, nullptr, nullptr, 0, nullptr, nullptr, part, nullptr, nullptr);

    // 4. fused: reduce M partials | dvec = s1*(db1 @ Ŵ1hiᵀ) + db2
    postgm_kernel<<<NB_RM + IN_DIM, 256>>>(part, Mhi, W1hi, db1, db2, cb1, dvec);

    // 5. G1: z1 = c19(s1*(x @ Ŵ1) + b1)   2-product   [4096 x 8192], K=2048
    gemm_fp16_kernel<8,2,1,4><<<dim3(HDIM / 256, NBATCH / BM), 256, SMEM_CFG(8,2,1,4)>>>(
        xhi, xlo, W1Thi, nullptr, NBATCH, HDIM, IN_DIM, IN_DIM,
        cb1, nullptr, b1, 1, craw, rraw, nullptr, z1hi, nullptr);

    // 6. G2: raw partials of z1hi @ Ŵ2 (1-product, K-split 4)  [4096 x 512], K=8192
    gemm_fp16_kernel<4,1,1,5><<<dim3(OUT_DIM / 128, NBATCH / BM, 4), 256, SMEM_CFG(4,1,1,5)>>>(
        z1hi, nullptr, W2Thi, nullptr, NBATCH, OUT_DIM, HDIM / 4, HDIM,
        nullptr, nullptr, nullptr, 0, nullptr, nullptr, part, nullptr, nullptr);

    // 7. reduce: z = s2*Σpartials + b2, + fp16 split
    {
        size_t n = (size_t)NBATCH * OUT_DIM;
        reduce_z_kernel<<<(unsigned)((n + 255) / 256), 256>>>(part, cb2, b2, z, zhi, zlo);
    }

    // 8. G5: dec = s1*s2*((zhi+zlo) @ M̂hiᵀ) + dvec  2-product  [4096 x 2048], K=512
    gemm_fp16_kernel<4,2,1,4><<<dim3(IN_DIM / 128, NBATCH / BM), 256, SMEM_CFG(4,2,1,4)>>>(
        zhi, zlo, Mhi, nullptr, NBATCH, IN_DIM, OUT_DIM, OUT_DIM,
        cb1, cb2, dvec, 0, nullptr, nullptr, dec, nullptr, nullptr);
}

// round 14
// speedup vs baseline: 1.0229x; 1.0229x over previous
#include <cuda_runtime.h>
#include <cuda_fp16.h>
#include <cstdint>

#define IN_DIM  2048
#define HDIM    8192
#define OUT_DIM 512
#define NBATCH  4096

typedef __half fp16;

// ---------------- scratch (static __device__ per harness rules) ----------------
__device__ __align__(256) fp16 g_xhi [(size_t)NBATCH * IN_DIM];
__device__ __align__(256) fp16 g_xlo [(size_t)NBATCH * IN_DIM];
__device__ __align__(256) fp16 g_W1hi[(size_t)IN_DIM * HDIM];     // Ŵ1 = W1/s1
__device__ __align__(256) fp16 g_W1Thi[(size_t)HDIM * IN_DIM];
__device__ __align__(256) fp16 g_W2Thi[(size_t)OUT_DIM * HDIM];   // Ŵ2ᵀ = (W2/s2)ᵀ
__device__ __align__(256) fp16 g_z1hi[(size_t)NBATCH * HDIM];
__device__ __align__(256) fp16 g_zhi [(size_t)NBATCH * OUT_DIM];
__device__ __align__(256) fp16 g_zlo [(size_t)NBATCH * OUT_DIM];
__device__ __align__(256) float g_part[(size_t)4 * IN_DIM * OUT_DIM]; // GM K-split partials
__device__ __align__(256) fp16 g_Mhi [(size_t)IN_DIM * OUT_DIM];  // M̂ = Ŵ1@Ŵ2
__device__ __align__(256) float g_dvec[IN_DIM];                   // db1@W1ᵀ + db2
__device__ int g_maskmode;

// ---------------- PTX helpers (compute_100-safe) ----------------
__device__ __forceinline__ uint32_t smem_u32(const void* p) {
    uint32_t a;
    asm("{ .reg .u64 t; cvta.to.shared.u64 t, %1; cvt.u32.u64 %0, t; }" : "=r"(a) : "l"(p));
    return a;
}
#define SWZ128(off) ((off) ^ (((off) >> 3) & 0x70))

__device__ __forceinline__ void cp16cp(uint32_t dst, const void* src) {
    asm volatile("cp.async.cg.shared.global [%0], [%1], 16;" :: "r"(dst), "l"(src));
}
#define CP_COMMIT() asm volatile("cp.async.commit_group;" ::: "memory")
#define CP_WAIT(n)  asm volatile("cp.async.wait_group %0;" :: "n"(n) : "memory")

__device__ __forceinline__ void ldsm4(uint32_t a, uint32_t& r0, uint32_t& r1,
                                      uint32_t& r2, uint32_t& r3) {
    asm volatile("ldmatrix.sync.aligned.m8n8.x4.shared.b16 {%0,%1,%2,%3}, [%4];"
                 : "=r"(r0), "=r"(r1), "=r"(r2), "=r"(r3) : "r"(a));
}

__device__ __forceinline__ void mma16816(float* d, const uint32_t* a, const uint32_t* b) {
    asm volatile("mma.sync.aligned.m16n8k16.row.col.f32.f16.f16.f32 "
        "{%0,%1,%2,%3}, {%4,%5,%6,%7}, {%8,%9}, {%0,%1,%2,%3};"
        : "+f"(d[0]), "+f"(d[1]), "+f"(d[2]), "+f"(d[3])
        : "r"(a[0]), "r"(a[1]), "r"(a[2]), "r"(a[3]), "r"(b[0]), "r"(b[1]));
}

// ---------------- mask dtype detection ----------------
__global__ void detect_mask_kernel(const unsigned int* __restrict__ m, int nwords) {
    __shared__ int ok[4];
    if (threadIdx.x < 4) ok[threadIdx.x] = 1;
    __syncthreads();
    for (int i = threadIdx.x; i < nwords; i += blockDim.x) {
        unsigned w = m[i];
        if (!(w == 0u || w == 1u))          atomicAnd(&ok[0], 0);
        if (!(w == 0u || w == 0x3F800000u)) atomicAnd(&ok[1], 0);
        unsigned lo = w & 0xFFFFu, hi = w >> 16;
        if (!((lo == 0u || lo == 0x3F80u) && (hi == 0u || hi == 0x3F80u))) atomicAnd(&ok[2], 0);
        if (!((lo == 0u || lo == 0x3C00u) && (hi == 0u || hi == 0x3C00u))) atomicAnd(&ok[3], 0);
    }
    __syncthreads();
    if (threadIdx.x == 0) {
        int mode = 0;
        if      (ok[0]) mode = 1;
        else if (ok[1]) mode = 2;
        else if (ok[2]) mode = 3;
        else if (ok[3]) mode = 4;
        g_maskmode = mode;
    }
}

__device__ __forceinline__ int read_mask(const void* p, long i, int mode) {
    switch (mode) {
        case 1:  return ((const int*)p)[i] != 0;
        case 2:  return ((const float*)p)[i] != 0.0f;
        case 3:  return ((const unsigned short*)p)[i] != 0;
        case 4:  return ((const unsigned short*)p)[i] != 0;
        default: return ((const unsigned char*)p)[i] != 0;
    }
}

__device__ __forceinline__ void split2h(float v, fp16& h, fp16& l) {
    h = __float2half(v);
    l = __float2half(v - __half2float(h));
}

// ---------------- fused prepass: split x | dequant W1 | dequant W2 ----------
#define NB_SPLIT (NBATCH * IN_DIM / 4 / 256)      // 8192
#define NB_DQ1   ((HDIM / 32) * (IN_DIM / 32))    // 16384
#define NB_DQ2   ((OUT_DIM / 32) * (HDIM / 32))   // 4096

__device__ __forceinline__ void dequant_block(
    const int* __restrict__ idx, const void* __restrict__ mask,
    const float* __restrict__ wf, const float* __restrict__ cb,
    fp16* __restrict__ Whi, fp16* __restrict__ WThi,
    int R, int C, int bx, int by, float tile[32][33]) {
    const int mode = g_maskmode;
    float s = __ldg(cb + 3);
    if (s == 0.0f) s = 1.0f;
    const int c0 = bx * 32;
    const int r0 = by * 32;
    const int tx = threadIdx.x & 31;
    const int ty = threadIdx.x >> 5;      // 0..7
    for (int rr = ty; rr < 32; rr += 8) {
        long off = (long)(r0 + rr) * C + c0 + tx;
        int  m = read_mask(mask, off, mode);
        float v = (m ? cb[idx[off]] : wf[off]) / s;   // exact for codebook
        if (Whi) Whi[off] = __float2half(v);
        tile[rr][tx] = v;
    }
    __syncthreads();
    for (int rr = ty; rr < 32; rr += 8) {
        float v = tile[tx][rr];
        long off = (long)(c0 + rr) * R + r0 + tx;
        WThi[off] = __float2half(v);
    }
}

__global__ void prepass_kernel(
    const float4* __restrict__ x4, fp16* __restrict__ xhi, fp16* __restrict__ xlo,
    const int* __restrict__ W1i, const void* __restrict__ W1m,
    const float* __restrict__ W1f, const float* __restrict__ cb1,
    fp16* __restrict__ W1hi, fp16* __restrict__ W1Thi,
    const int* __restrict__ W2i, const void* __restrict__ W2m,
    const float* __restrict__ W2f, const float* __restrict__ cb2,
    fp16* __restrict__ W2Thi) {
    __shared__ float tile[32][33];
    const int b = blockIdx.x;
    if (b < NB_SPLIT) {
        size_t i = (size_t)b * 256 + threadIdx.x;
        float4 v = x4[i];
        fp16 h0, l0, h1, l1, h2, l2, h3, l3;
        split2h(v.x, h0, l0); split2h(v.y, h1, l1);
        split2h(v.z, h2, l2); split2h(v.w, h3, l3);
        ((__half2*)xhi)[2 * i]     = __halves2half2(h0, h1);
        ((__half2*)xhi)[2 * i + 1] = __halves2half2(h2, h3);
        ((__half2*)xlo)[2 * i]     = __halves2half2(l0, l1);
        ((__half2*)xlo)[2 * i + 1] = __halves2half2(l2, l3);
    } else if (b < NB_SPLIT + NB_DQ1) {
        int j = b - NB_SPLIT;
        dequant_block(W1i, W1m, W1f, cb1, W1hi, W1Thi,
                      IN_DIM, HDIM, j & 255, j >> 8, tile);
    } else {
        int j = b - NB_SPLIT - NB_DQ1;
        dequant_block(W2i, W2m, W2f, cb2, nullptr, W2Thi,
                      HDIM, OUT_DIM, j & 15, j >> 4, tile);
    }
}

// ---------------- fused post-GM: reduce M partials | dvec ----------------
#define NB_RM ((IN_DIM * OUT_DIM) / 256)          // 4096

__global__ void postgm_kernel(const float* __restrict__ part,
                              fp16* __restrict__ Mhi,
                              const fp16* __restrict__ W1hi,
                              const float* __restrict__ db1, const float* __restrict__ db2,
                              const float* __restrict__ cb1, float* __restrict__ dvec) {
    __shared__ float red[256];
    const int b = blockIdx.x;
    if (b < NB_RM) {
        size_t i = (size_t)b * 256 + threadIdx.x;
        const size_t n = (size_t)IN_DIM * OUT_DIM;
        float v = part[i] + part[i + n] + part[i + 2 * n] + part[i + 3 * n];
        Mhi[i] = __float2half(v);
    } else {
        const int j = b - NB_RM;
        float s = __ldg(cb1 + 3);
        if (s == 0.0f) s = 1.0f;
        float sum = 0.0f;
        const size_t base = (size_t)j * HDIM;
        for (int h = threadIdx.x; h < HDIM; h += 256)
            sum += __half2float(W1hi[base + h]) * __ldg(db1 + h);
        red[threadIdx.x] = sum;
        __syncthreads();
        for (int st = 128; st > 0; st >>= 1) {
            if (threadIdx.x < st) red[threadIdx.x] += red[threadIdx.x + st];
            __syncthreads();
        }
        if (threadIdx.x == 0) dvec[j] = fmaf(s, red[0], __ldg(db2 + j));
    }
}

// ---------------- c19 activation ----------------
__device__ __forceinline__ float c19f(float x, float craw, float rhoraw) {
    float c   = fmaxf(craw, 0.1f);
    float rho = fmaxf(rhoraw, 0.0f);
    float L   = 6.0f * c;
    float s   = x / c;
    float n   = floorf(s);
    float t   = s - n;
    float h   = t * (1.0f - t);
    float sgn = (fmodf(n, 2.0f) == 0.0f) ? 1.0f : -1.0f;
    float interior = c * (sgn * h + rho * h * h);
    return (x >= L) ? (x - L) : ((x <= -L) ? (x + L) : interior);
}

// ---------------- fp16 multi-product GEMM ----------------
// acc = Ahi*Bhi (+ Alo*Bhi if PA==2) (+ Ahi*Blo if PB==2)
// C = sa*sb*acc + bias (nullable). B K-major. Block 128 x (NI*32), 8 warps 2x4.
// gridDim.z = K-splits (partials at Cf + z*M*Nn). ldk = row stride of A and B.
#define BM 128
#define BKK 32

template<int NI, int PA, int PB, int NSTAGE>
__global__ void __launch_bounds__(256, 1)
gemm_fp16_kernel(const fp16* __restrict__ Ahi, const fp16* __restrict__ Alo,
                 const fp16* __restrict__ Bhi, const fp16* __restrict__ Blo,
                 int M, int Nn, int Klen, int ldk,
                 const float* __restrict__ cba, const float* __restrict__ cbb,
                 const float* __restrict__ bias, int epi,
                 const float* __restrict__ craw, const float* __restrict__ rho,
                 float* __restrict__ Cf, fp16* __restrict__ Chi, fp16* __restrict__ Clo) {
    constexpr int BN = NI * 32;
    constexpr int A_BYTES = BM * 64;
    constexpr int B_BYTES = BN * 64;
    constexpr int STAGE_BYTES = PA * A_BYTES + PB * B_BYTES;
    extern __shared__ char smem[];
    const uint32_t sbase = smem_u32(smem);
    const uint32_t tbase = (sbase + 1023u) & ~1023u;
    const int tid  = threadIdx.x;
    const int wid  = tid >> 5;
    const int lane = tid & 31;
    const int wm = wid & 1;
    const int wn = wid >> 1;

    const int m0 = blockIdx.y * BM;
    const int n0 = blockIdx.x * BN;
    const size_t kbase = (size_t)blockIdx.z * Klen;

    float sa = cba ? __ldg(cba + 3) : 1.0f;  if (sa == 0.0f) sa = 1.0f;
    float sb = cbb ? __ldg(cbb + 3) : 1.0f;  if (sb == 0.0f) sb = 1.0f;
    const float sc = sa * sb;

    uint32_t sAh[NSTAGE], sAl[NSTAGE], sBh[NSTAGE], sBl[NSTAGE];
#pragma unroll
    for (int s = 0; s < NSTAGE; s++) {
        uint32_t b = tbase + s * STAGE_BYTES;
        sAh[s] = b;
        sAl[s] = b + A_BYTES;                         // valid if PA==2
        sBh[s] = b + PA * A_BYTES;
        sBl[s] = b + PA * A_BYTES + B_BYTES;          // valid if PB==2
    }

    const int ITERS = Klen / BKK;

    float acc[4][NI][4];
#pragma unroll
    for (int i = 0; i < 4; i++)
#pragma unroll
        for (int j = 0; j < NI; j++)
#pragma unroll
            for (int r = 0; r < 4; r++) acc[i][j][r] = 0.0f;

    auto fill = [&](int kc) {
        const int s = kc % NSTAGE;
        const size_t k0 = kbase + (size_t)kc * BKK;
#pragma unroll
        for (int i = 0; i < 2; i++) {
            int ch = tid + i * 256;
            int r = ch >> 2, c = ch & 3;
            uint32_t so = SWZ128(r * 64 + c * 16);
            const char* pA = (const char*)(Ahi + (size_t)(m0 + r) * ldk + k0) + c * 16;
            cp16cp(sAh[s] + so, pA);
            if (PA == 2) {
                const char* pL = (const char*)(Alo + (size_t)(m0 + r) * ldk + k0) + c * 16;
                cp16cp(sAl[s] + so, pL);
            }
        }
#pragma unroll
        for (int i = 0; i < NI / 2; i++) {
            int ch = tid + i * 256;
            int r = ch >> 2, c = ch & 3;
            uint32_t so = SWZ128(r * 64 + c * 16);
            const char* pB = (const char*)(Bhi + (size_t)(n0 + r) * ldk + k0) + c * 16;
            cp16cp(sBh[s] + so, pB);
            if (PB == 2) {
                const char* pBl = (const char*)(Blo + (size_t)(n0 + r) * ldk + k0) + c * 16;
                cp16cp(sBl[s] + so, pBl);
            }
        }
    };

    // prologue
    for (int it = 0; it < NSTAGE - 1; it++) { fill(it); CP_COMMIT(); }

    for (int it = 0; it < ITERS; it++) {
        CP_WAIT(NSTAGE - 2);
        __syncthreads();
        if (it + NSTAGE - 1 < ITERS) fill(it + NSTAGE - 1);
        CP_COMMIT();

        const int s = it % NSTAGE;
#pragma unroll
        for (int kk = 0; kk < 2; kk++) {
            uint32_t afh[4][4], afl[4][4];
#pragma unroll
            for (int mi = 0; mi < 4; mi++) {
                int row = wm * 64 + mi * 16 + (lane & 15);
                int ch  = kk * 2 + (lane >> 4);
                uint32_t so = SWZ128(row * 64 + ch * 16);
                ldsm4(sAh[s] + so, afh[mi][0], afh[mi][1], afh[mi][2], afh[mi][3]);
                if (PA == 2)
                    ldsm4(sAl[s] + so, afl[mi][0], afl[mi][1], afl[mi][2], afl[mi][3]);
            }
            uint32_t bfh[NI][2], bfl[NI][2];
#pragma unroll
            for (int p = 0; p < NI / 2; p++) {
                int g   = lane >> 3;
                int row = wn * (NI * 8) + (p * 2 + (g >> 1)) * 8 + (lane & 7);
                int ch  = kk * 2 + (g & 1);
                uint32_t so = SWZ128(row * 64 + ch * 16);
                uint32_t r0, r1, r2, r3;
                ldsm4(sBh[s] + so, r0, r1, r2, r3);
                bfh[p * 2][0] = r0;  bfh[p * 2][1] = r1;
                bfh[p * 2 + 1][0] = r2; bfh[p * 2 + 1][1] = r3;
                if (PB == 2) {
                    ldsm4(sBl[s] + so, r0, r1, r2, r3);
                    bfl[p * 2][0] = r0;  bfl[p * 2][1] = r1;
                    bfl[p * 2 + 1][0] = r2; bfl[p * 2 + 1][1] = r3;
                }
            }
#pragma unroll
            for (int mi = 0; mi < 4; mi++)
#pragma unroll
                for (int ni = 0; ni < NI; ni++)
                    mma16816(acc[mi][ni], afh[mi], bfh[ni]);
            if (PA == 2) {
#pragma unroll
                for (int mi = 0; mi < 4; mi++)
#pragma unroll
                    for (int ni = 0; ni < NI; ni++)
                        mma16816(acc[mi][ni], afl[mi], bfh[ni]);
            }
            if (PB == 2) {
#pragma unroll
                for (int mi = 0; mi < 4; mi++)
#pragma unroll
                    for (int ni = 0; ni < NI; ni++)
                        mma16816(acc[mi][ni], afh[mi], bfl[ni]);
            }
        }
    }

    // ---------------- epilogue: scale + bias (+c19) + outputs ----------------
    float* CfZ = Cf ? Cf + (size_t)blockIdx.z * M * Nn : nullptr;
#pragma unroll
    for (int ni = 0; ni < NI; ni++) {
        const int n = n0 + wn * (NI * 8) + ni * 8 + 2 * (lane & 3);
        const float bv0 = bias ? __ldg(bias + n)     : 0.0f;
        const float bv1 = bias ? __ldg(bias + n + 1) : 0.0f;
        float c0 = 0, c1 = 0, r0 = 0, r1 = 0;
        if (epi) {
            c0 = __ldg(craw + n);  c1 = __ldg(craw + n + 1);
            r0 = __ldg(rho + n);   r1 = __ldg(rho + n + 1);
        }
#pragma unroll
        for (int mi = 0; mi < 4; mi++) {
#pragma unroll
            for (int h = 0; h < 2; h++) {
                const int m = m0 + wm * 64 + mi * 16 + (lane >> 2) + h * 8;
                float v0 = fmaf(sc, acc[mi][ni][2 * h],     bv0);
                float v1 = fmaf(sc, acc[mi][ni][2 * h + 1], bv1);
                if (epi) { v0 = c19f(v0, c0, r0); v1 = c19f(v1, c1, r1); }
                const size_t off = (size_t)m * Nn + n;
                if (CfZ) *(float2*)(CfZ + off) = make_float2(v0, v1);
                if (Chi) {
                    fp16 h0, l0, h1, l1;
                    split2h(v0, h0, l0); split2h(v1, h1, l1);
                    *(__half2*)(Chi + off) = __halves2half2(h0, h1);
                    if (Clo) *(__half2*)(Clo + off) = __halves2half2(l0, l1);
                }
            }
        }
    }
}

#define SMEM_CFG(NI, PA, PB, NSTAGE) \
    (1024 + (NSTAGE) * ((PA) * BM * 64 + (PB) * (NI) * 32 * 64))

// ---------------- launch ----------------
extern "C" void kernel_launch(void* const* d_in, const int* in_sizes, int n_in,
                              void* d_out, int out_size) {
    const float* x    = (const float*)d_in[0];
    const float* cb1  = (const float*)d_in[1];
    const float* cb2  = (const float*)d_in[2];
    const float* W1f  = (const float*)d_in[3];
    const float* W2f  = (const float*)d_in[4];
    const float* b1   = (const float*)d_in[5];
    const float* b2   = (const float*)d_in[6];
    const float* db1  = (const float*)d_in[7];
    const float* db2  = (const float*)d_in[8];
    const float* craw = (const float*)d_in[9];
    const float* rraw = (const float*)d_in[10];
    const int*   W1i  = (const int*)d_in[11];
    const int*   W2i  = (const int*)d_in[12];
    const void*  W1m  = d_in[13];
    const void*  W2m  = d_in[14];

    fp16 *xhi, *xlo, *W1hi, *W1Thi, *W2Thi;
    fp16 *z1hi, *zhi, *zlo, *Mhi;
    float *part, *dvec;
    cudaGetSymbolAddress((void**)&xhi,  g_xhi);   cudaGetSymbolAddress((void**)&xlo,  g_xlo);
    cudaGetSymbolAddress((void**)&W1hi, g_W1hi);
    cudaGetSymbolAddress((void**)&W1Thi,g_W1Thi);
    cudaGetSymbolAddress((void**)&W2Thi,g_W2Thi);
    cudaGetSymbolAddress((void**)&z1hi, g_z1hi);
    cudaGetSymbolAddress((void**)&zhi,  g_zhi);   cudaGetSymbolAddress((void**)&zlo,  g_zlo);
    cudaGetSymbolAddress((void**)&part, g_part);
    cudaGetSymbolAddress((void**)&Mhi,  g_Mhi);
    cudaGetSymbolAddress((void**)&dvec, g_dvec);

    float* dec = (float*)d_out;
    float* z   = (float*)d_out + (size_t)NBATCH * IN_DIM;

    cudaFuncSetAttribute((const void*)gemm_fp16_kernel<8,2,1,4>,
                         cudaFuncAttributeMaxDynamicSharedMemorySize, SMEM_CFG(8,2,1,4));
    cudaFuncSetAttribute((const void*)gemm_fp16_kernel<4,1,1,5>,
                         cudaFuncAttributeMaxDynamicSharedMemorySize, SMEM_CFG(4,1,1,5));
    cudaFuncSetAttribute((const void*)gemm_fp16_kernel<4,2,1,4>,
                         cudaFuncAttributeMaxDynamicSharedMemorySize, SMEM_CFG(4,2,1,4));

    // 1. mask dtype probe
    detect_mask_kernel<<<1, 256>>>((const unsigned int*)W1m, 4096);

    // 2. fused prepass: split x | dequant W1 | dequant W2 (overlapped)
    prepass_kernel<<<NB_SPLIT + NB_DQ1 + NB_DQ2, 256>>>(
        (const float4*)x, xhi, xlo,
        W1i, W1m, W1f, cb1, W1hi, W1Thi,
        W2i, W2m, W2f, cb2, W2Thi);

    // 3. GM: M̂ = Ŵ1hi @ Ŵ2hi (1-product, K-split 4)   [2048 x 512], K=8192
    gemm_fp16_kernel<4,1,1,5><<<dim3(OUT_DIM / 128, IN_DIM / BM, 4), 256, SMEM_CFG(4,1,1,5)>>>(
        W1hi, nullptr, W2Thi, nullptr, IN_DIM, OUT_DIM, HDIM / 4, HDIM,
        nullptr, nullptr, nullptr, 0, nullptr, nullptr, part, nullptr, nullptr);

    // 4. fused: reduce M partials | dvec = s1*(db1 @ Ŵ1hiᵀ) + db2
    postgm_kernel<<<NB_RM + IN_DIM, 256>>>(part, Mhi, W1hi, db1, db2, cb1, dvec);

    // 5. G1: z1 = c19(s1*(x @ Ŵ1) + b1)   2-product   [4096 x 8192], K=2048
    gemm_fp16_kernel<8,2,1,4><<<dim3(HDIM / 256, NBATCH / BM), 256, SMEM_CFG(8,2,1,4)>>>(
        xhi, xlo, W1Thi, nullptr, NBATCH, HDIM, IN_DIM, IN_DIM,
        cb1, nullptr, b1, 1, craw, rraw, nullptr, z1hi, nullptr);

    // 6. G2: z = s2*(z1hi @ Ŵ2) + b2      1-product, direct   [4096 x 512], K=8192
    gemm_fp16_kernel<4,1,1,5><<<dim3(OUT_DIM / 128, NBATCH / BM), 256, SMEM_CFG(4,1,1,5)>>>(
        z1hi, nullptr, W2Thi, nullptr, NBATCH, OUT_DIM, HDIM, HDIM,
        cb2, nullptr, b2, 0, nullptr, nullptr, z, zhi, zlo);

    // 7. G5: dec = s1*s2*((zhi+zlo) @ M̂hiᵀ) + dvec  2-product  [4096 x 2048], K=512
    gemm_fp16_kernel<4,2,1,4><<<dim3(IN_DIM / 128, NBATCH / BM), 256, SMEM_CFG(4,2,1,4)>>>(
        zhi, zlo, Mhi, nullptr, NBATCH, IN_DIM, OUT_DIM, OUT_DIM,
        cb1, cb2, dvec, 0, nullptr, nullptr, dec, nullptr, nullptr);
}